// round 1
// baseline (speedup 1.0000x reference)
#include <cuda_runtime.h>

#define B   16
#define KV  8192
#define D   1024
#define D4  256        // D / 4 (float4 count per row)
#define SS  8224       // score stride per batch (>= KV+1, padded)
#define NSPLIT 32      // k-splits in the A*V kernel

// ---------------- device scratch (no allocations allowed) ----------------
__device__ float g_q [B * D];
__device__ float g_nk[B * D];
__device__ float g_nv[B * D];
__device__ float g_scores[B * SS];                 // scores, then softmax weights in place
__device__ float g_partial[B * NSPLIT * D];        // partial outputs per k-split

// ---------------- K0: projections q/new_k/new_v = x @ W^T ----------------
// grid (384, 2), block 256. 8 warps/block, 1 output row each, 8 batches per block.
__global__ void proj_kernel(const float* __restrict__ x,
                            const float* __restrict__ wq,
                            const float* __restrict__ wk,
                            const float* __restrict__ wv) {
    __shared__ float4 xs[8 * D4];   // 8 batches of x, 32 KB
    const int tid  = threadIdx.x;
    const int warp = tid >> 5;
    const int lane = tid & 31;
    const int grp  = blockIdx.y;    // batch group (0 or 1)

    const float4* x4 = (const float4*)x;
    for (int i = tid; i < 8 * D4; i += 256) xs[i] = x4[grp * 8 * D4 + i];
    __syncthreads();

    const int row = blockIdx.x * 8 + warp;   // 0..3071
    const int mat = row >> 10;
    const int e   = row & 1023;
    const float* W  = (mat == 0) ? wq  : (mat == 1) ? wk  : wv;
    float*      out = (mat == 0) ? g_q : (mat == 1) ? g_nk : g_nv;
    const float4* W4 = (const float4*)W;

    float acc[8];
#pragma unroll
    for (int b = 0; b < 8; b++) acc[b] = 0.f;

#pragma unroll
    for (int ii = 0; ii < 8; ii++) {
        const int i = lane + ii * 32;
        const float4 w4 = W4[e * D4 + i];
#pragma unroll
        for (int b = 0; b < 8; b++) {
            const float4 xv = xs[b * D4 + i];
            acc[b] += w4.x * xv.x + w4.y * xv.y + w4.z * xv.z + w4.w * xv.w;
        }
    }
#pragma unroll
    for (int b = 0; b < 8; b++) {
#pragma unroll
        for (int o = 16; o > 0; o >>= 1)
            acc[b] += __shfl_xor_sync(0xffffffffu, acc[b], o);
    }
    if (lane == 0) {
#pragma unroll
        for (int b = 0; b < 8; b++)
            out[(grp * 8 + b) * D + e] = acc[b];
    }
}

// ---------------- K1: scores[b][k] = q[b] . cache_k[b][k] / sqrt(D) ----------------
// grid (32, 16), block 256 (8 warps). One warp per key, 32 keys/warp.
__global__ void scores_kernel(const float* __restrict__ cache_k) {
    const int b    = blockIdx.y;
    const int tid  = threadIdx.x;
    const int warp = tid >> 5;
    const int lane = tid & 31;

    __shared__ float4 qs[D4];   // 4 KB
    const float4* q4 = (const float4*)g_q + b * D4;
    for (int i = tid; i < D4; i += 256) qs[i] = q4[i];
    __syncthreads();

    const float4* K4 = (const float4*)cache_k;
    const int key_base = blockIdx.x * 256;

#pragma unroll 1
    for (int j = 0; j < 32; j++) {
        const int key = key_base + warp + j * 8;
        const float4* row = K4 + (size_t)(b * KV + key) * D4;
        float acc = 0.f;
#pragma unroll
        for (int ii = 0; ii < 8; ii++) {
            const int i = lane + ii * 32;
            const float4 kv = row[i];
            const float4 qq = qs[i];
            acc += kv.x * qq.x + kv.y * qq.y + kv.z * qq.z + kv.w * qq.w;
        }
#pragma unroll
        for (int o = 16; o > 0; o >>= 1)
            acc += __shfl_xor_sync(0xffffffffu, acc, o);
        if (lane == 0)
            g_scores[b * SS + key] = acc * 0.03125f;   // 1/sqrt(1024)
    }
}

// ---------------- K2: appended-key score + softmax (weights in place) ----------------
// grid 16, block 256.
__global__ void softmax_kernel() {
    const int b   = blockIdx.x;
    const int tid = threadIdx.x;
    __shared__ float red[256];
    float* sc = g_scores + b * SS;

    // score for the new (appended) key
    float p = 0.f;
    for (int i = tid; i < D; i += 256) p += g_q[b * D + i] * g_nk[b * D + i];
    red[tid] = p; __syncthreads();
    for (int s = 128; s > 0; s >>= 1) {
        if (tid < s) red[tid] += red[tid + s];
        __syncthreads();
    }
    if (tid == 0) sc[KV] = red[0] * 0.03125f;
    __syncthreads();

    // max over KV+1 scores
    float m = -1e30f;
    for (int i = tid; i <= KV; i += 256) m = fmaxf(m, sc[i]);
    red[tid] = m; __syncthreads();
    for (int s = 128; s > 0; s >>= 1) {
        if (tid < s) red[tid] = fmaxf(red[tid], red[tid + s]);
        __syncthreads();
    }
    m = red[0];
    __syncthreads();

    // sum of exp
    float sum = 0.f;
    for (int i = tid; i <= KV; i += 256) sum += __expf(sc[i] - m);
    red[tid] = sum; __syncthreads();
    for (int s = 128; s > 0; s >>= 1) {
        if (tid < s) red[tid] += red[tid + s];
        __syncthreads();
    }
    const float inv = 1.f / red[0];
    __syncthreads();

    // normalize in place -> attention weights
    for (int i = tid; i <= KV; i += 256)
        sc[i] = __expf(sc[i] - m) * inv;
}

// ---------------- K3: partial out = sum_k w[k] * v[k][dslice] ----------------
// grid (2 dslices, NSPLIT ksplits, 16 batches), block 128. float4 per thread.
__global__ void av_kernel(const float* __restrict__ cache_v) {
    const int slice = blockIdx.x;      // 0..1   (512 cols each)
    const int split = blockIdx.y;      // 0..NSPLIT-1
    const int b     = blockIdx.z;
    const int tid   = threadIdx.x;     // 0..127
    const int keys_per = KV / NSPLIT;  // 256

    __shared__ float ws[KV / NSPLIT];
    const int key0 = split * keys_per;
    for (int i = tid; i < keys_per; i += 128)
        ws[i] = g_scores[b * SS + key0 + i];
    __syncthreads();

    const float4* V4 = (const float4*)cache_v;
    const int col = slice * 128 + tid;                 // float4 column 0..255
    const float4* base = V4 + (size_t)(b * KV + key0) * D4 + col;

    float4 acc = make_float4(0.f, 0.f, 0.f, 0.f);
#pragma unroll 8
    for (int k = 0; k < keys_per; k++) {
        const float  w = ws[k];
        const float4 v = base[(size_t)k * D4];
        acc.x += w * v.x; acc.y += w * v.y;
        acc.z += w * v.z; acc.w += w * v.w;
    }
    ((float4*)g_partial)[(size_t)(b * NSPLIT + split) * D4 + col] = acc;
}

// ---------------- K4: combine splits + new-v term, round(.,4), write out ----------------
// grid 16, block 256.
__global__ void reduce_kernel(float* __restrict__ out) {
    const int b   = blockIdx.x;
    const int tid = threadIdx.x;       // float4 column
    const float4* P4 = (const float4*)g_partial;

    float4 acc = make_float4(0.f, 0.f, 0.f, 0.f);
#pragma unroll
    for (int s = 0; s < NSPLIT; s++) {
        const float4 p = P4[(size_t)(b * NSPLIT + s) * D4 + tid];
        acc.x += p.x; acc.y += p.y; acc.z += p.z; acc.w += p.w;
    }
    const float wn = g_scores[b * SS + KV];
    const float4 nv = ((const float4*)g_nv)[b * D4 + tid];
    acc.x += wn * nv.x; acc.y += wn * nv.y;
    acc.z += wn * nv.z; acc.w += wn * nv.w;

    acc.x = rintf(acc.x * 10000.f) / 10000.f;
    acc.y = rintf(acc.y * 10000.f) / 10000.f;
    acc.z = rintf(acc.z * 10000.f) / 10000.f;
    acc.w = rintf(acc.w * 10000.f) / 10000.f;
    ((float4*)out)[b * D4 + tid] = acc;
}

// ---------------- launcher ----------------
extern "C" void kernel_launch(void* const* d_in, const int* in_sizes, int n_in,
                              void* d_out, int out_size) {
    const float* x  = (const float*)d_in[0];
    const float* ck = (const float*)d_in[1];
    const float* cv = (const float*)d_in[2];
    const float* wq = (const float*)d_in[3];
    const float* wk = (const float*)d_in[4];
    const float* wv = (const float*)d_in[5];
    float* out = (float*)d_out;

    proj_kernel   <<<dim3(384, 2), 256>>>(x, wq, wk, wv);
    scores_kernel <<<dim3(32, B),  256>>>(ck);
    softmax_kernel<<<B,            256>>>();
    av_kernel     <<<dim3(2, NSPLIT, B), 128>>>(cv);
    reduce_kernel <<<B,            256>>>(out);
}